// round 9
// baseline (speedup 1.0000x reference)
#include <cuda_runtime.h>
#include <math.h>

#define IM     256
#define NSP    288
#define NSAMP  640
#define MTOT   (NSP*NSAMP)        // 184320
#define NCHUNK 36                 // spoke chunks for adjoint partials
#define SPC    (NSP/NCHUNK)       // 8 spokes per chunk
#define ORTHO_F (1.0f/256.0f)     // 1/sqrt(256*256)

typedef unsigned long long u64;

// Scratch (allocation-free rule: __device__ globals)
__device__ float2 g_kdc[MTOT];                 // blended k-space, 1.5 MB
__device__ float2 g_part[NCHUNK*IM*IM];        // adjoint partials, 18.9 MB

__device__ __forceinline__ float2 cmulf(float2 a, float2 b) {
    return make_float2(fmaf(a.x, b.x, -(a.y*b.y)), fmaf(a.x, b.y, a.y*b.x));
}
__device__ __forceinline__ float2 expif(float t) {
    float s, c; sincosf(t, &s, &c); return make_float2(c, s);
}

// ---- packed f32x2 helpers (sm_103a FFMA2 path) ----
__device__ __forceinline__ u64 pk2(float lo, float hi) {
    u64 r; asm("mov.b64 %0, {%1, %2};" : "=l"(r) : "f"(lo), "f"(hi)); return r;
}
__device__ __forceinline__ void upk2(u64 v, float& lo, float& hi) {
    asm("mov.b64 {%0, %1}, %2;" : "=f"(lo), "=f"(hi) : "l"(v));
}
__device__ __forceinline__ u64 f2fma(u64 a, u64 b, u64 c) {
    u64 d; asm("fma.rn.f32x2 %0, %1, %2, %3;" : "=l"(d) : "l"(a), "l"(b), "l"(c)); return d;
}
__device__ __forceinline__ u64 f2mul(u64 a, u64 b) {
    u64 d; asm("mul.rn.f32x2 %0, %1, %2;" : "=l"(d) : "l"(a), "l"(b)); return d;
}
__device__ __forceinline__ u64 swp(u64 v) {
    float a, b; upk2(v, a, b); return pk2(b, a);
}

// ---------------------------------------------------------------------------
// Kernel A: forward NDFT + DCF + sigmoid blend.  One thread per k-sample m.
// Complex MAC split into two broadcast-scaled packed sums per w:
//   S1[w] += (ex.x,ex.x) * (d.x,d.y) ;  S2[w] += (ex.y,ex.y) * (d.x,d.y)
// combine at panel end:  acc[w] = (S1.x - S2.y, S1.y + S2.x).
// ---------------------------------------------------------------------------
#define BN 16
__global__ void __launch_bounds__(256) fwd_kernel(
    const float2* __restrict__ img,          // [256][256] (re,im)
    const float2* __restrict__ yrad,         // [640][288] (re,im)
    const float*  __restrict__ lambda_param, // [1]
    const float*  __restrict__ kx,           // [M]
    const float*  __restrict__ ky)           // [M]
{
    __shared__ float2 panel[IM*BN];          // 32 KB, [u][w]

    const int m   = blockIdx.x * 256 + threadIdx.x;
    const float kxm = kx[m];
    const float kym = ky[m];

    const float2 stepx = expif(-kxm);          // e^{-i kx} per u step
    const float2 ex0   = expif(128.0f * kxm);  // e^{-i kx * (-128)}
    const float2 stepy = expif(-kym);
    float2 A = make_float2(0.0f, 0.0f);

    #pragma unroll 1
    for (int p = 0; p < IM/BN; ++p) {
        __syncthreads();
        for (int idx = threadIdx.x; idx < IM*BN; idx += 256) {
            int u = idx >> 4, w = idx & (BN-1);
            panel[idx] = img[u*IM + p*BN + w];
        }
        __syncthreads();

        u64 S1[BN], S2[BN];
        #pragma unroll
        for (int w = 0; w < BN; ++w) { S1[w] = 0ull; S2[w] = 0ull; }

        float2 ex = ex0;
        #pragma unroll 2
        for (int u = 0; u < IM; ++u) {
            const u64 exx = pk2(ex.x, ex.x);
            const u64 exy = pk2(ex.y, ex.y);
            const ulonglong2* row = reinterpret_cast<const ulonglong2*>(&panel[u*BN]);
            #pragma unroll
            for (int w2 = 0; w2 < BN/2; ++w2) {
                ulonglong2 dd = row[w2];            // 2 complex pixels, LDS.128 broadcast
                S1[2*w2  ] = f2fma(exx, dd.x, S1[2*w2  ]);
                S2[2*w2  ] = f2fma(exy, dd.x, S2[2*w2  ]);
                S1[2*w2+1] = f2fma(exx, dd.y, S1[2*w2+1]);
                S2[2*w2+1] = f2fma(exy, dd.y, S2[2*w2+1]);
            }
            ex = cmulf(ex, stepx);
        }

        // fold panel accumulators with e^{-i ky * v}, v = p*BN + w - 128
        float2 ey = expif(-kym * (float)(p*BN - 128));
        #pragma unroll
        for (int w = 0; w < BN; ++w) {
            float s1x, s1y, s2x, s2y;
            upk2(S1[w], s1x, s1y); upk2(S2[w], s2x, s2y);
            const float cx = s1x - s2y;
            const float cy = s1y + s2x;
            A.x = fmaf(cx, ey.x, A.x); A.x = fmaf(-cy, ey.y, A.x);
            A.y = fmaf(cx, ey.y, A.y); A.y = fmaf( cy, ey.x, A.y);
            ey = cmulf(ey, stepy);
        }
    }

    // epilogue: ortho scale, ramp DCF, sigmoid blend with measured data
    A.x *= ORTHO_F; A.y *= ORTHO_F;
    const float lam = 1.0f / (1.0f + expf(-lambda_param[0]));
    const float dcf = sqrtf(kxm*kxm + kym*kym);
    const int t = m % NSAMP, s = m / NSAMP;
    const float2 yv = yrad[t*NSP + s];          // y_radial is (640, 288, 2)
    const float a = lam * dcf, b = 1.0f - lam;
    g_kdc[m] = make_float2(fmaf(a, A.x, b*yv.x), fmaf(a, A.y, b*yv.y));
}

// ---------------------------------------------------------------------------
// Kernel B: adjoint NDFT, fully packed.
// Per output, single packed accumulator:
//   acc += (qx,qx)*pu + (-qy,qy)*swap(pu)          [= acc + pu*q complex]
// Phase recurrences packed:  p <- sA*p + sB*swap(p) [= p*s complex], with
// sA=(s.x,s.x), sB=(-s.y,s.y) hoisted per spoke.  swap(pu) is shared between
// the MAC and the recurrence.
// ---------------------------------------------------------------------------
__global__ void __launch_bounds__(256) adj_kernel(
    const float* __restrict__ kx, const float* __restrict__ ky)
{
    const int u0 = (blockIdx.x & 1) * 128;
    const int w0 = (blockIdx.x >> 1) * 64;
    const int chunk = blockIdx.y;
    const int tr = threadIdx.x >> 4;   // 0..15
    const int tc = threadIdx.x & 15;   // 0..15

    float U[8], W[4];
    #pragma unroll
    for (int i = 0; i < 8; ++i) U[i] = (float)(u0 + tr + i*16 - 128);
    #pragma unroll
    for (int j = 0; j < 4; ++j) W[j] = (float)(w0 + tc + j*16 - 128);

    u64 acc[8][4];
    #pragma unroll
    for (int i = 0; i < 8; ++i)
        #pragma unroll
        for (int j = 0; j < 4; ++j) acc[i][j] = 0ull;

    #pragma unroll 1
    for (int sp = 0; sp < SPC; ++sp) {
        const int s  = chunk*SPC + sp;
        const int m0 = s*NSAMP;
        const float kx0 = kx[m0], ky0 = ky[m0];
        // endpoint-fitted slope: slope error ~1e-9 -> phase error ~1e-4 rad max
        const float dkx = (kx[m0+NSAMP-1] - kx0) * (1.0f/(float)(NSAMP-1));
        const float dky = (ky[m0+NSAMP-1] - ky0) * (1.0f/(float)(NSAMP-1));

        u64 pu[8], suA[8], suB[8], pw[4], swA[4], swB[4];
        #pragma unroll
        for (int i = 0; i < 8; ++i) {
            float2 e = expif(kx0*U[i]);  pu[i]  = pk2(e.x, e.y);
            float2 d = expif(dkx*U[i]);  suA[i] = pk2(d.x, d.x); suB[i] = pk2(-d.y, d.y);
        }
        #pragma unroll
        for (int j = 0; j < 4; ++j) {
            float2 e = expif(ky0*W[j]);  pw[j]  = pk2(e.x, e.y);
            float2 d = expif(dky*W[j]);  swA[j] = pk2(d.x, d.x); swB[j] = pk2(-d.y, d.y);
        }

        #pragma unroll 2
        for (int t = 0; t < NSAMP; ++t) {
            const float2 k = g_kdc[m0 + t];        // uniform address -> broadcast
            const u64 kxx = pk2(k.x, k.x);
            const u64 kyn = pk2(-k.y, k.y);

            u64 qxx[4], qyn[4];
            #pragma unroll
            for (int j = 0; j < 4; ++j) {
                const u64 spw = swp(pw[j]);
                const u64 q = f2fma(kyn, spw, f2mul(kxx, pw[j]));  // k * pw[j]
                float qx, qy; upk2(q, qx, qy);
                qxx[j] = pk2(qx, qx);
                qyn[j] = pk2(-qy, qy);
                pw[j] = f2fma(swB[j], spw, f2mul(swA[j], pw[j]));  // pw *= sw
            }
            #pragma unroll
            for (int i = 0; i < 8; ++i) {
                const u64 spu = swp(pu[i]);
                #pragma unroll
                for (int j = 0; j < 4; ++j) {
                    acc[i][j] = f2fma(qxx[j], pu[i], acc[i][j]);
                    acc[i][j] = f2fma(qyn[j], spu,   acc[i][j]);
                }
                pu[i] = f2fma(suB[i], spu, f2mul(suA[i], pu[i]));  // pu *= su
            }
        }
    }

    float2* part = g_part + (size_t)chunk * (IM*IM);
    #pragma unroll
    for (int i = 0; i < 8; ++i)
        #pragma unroll
        for (int j = 0; j < 4; ++j) {
            float ax, ay; upk2(acc[i][j], ax, ay);
            part[(u0 + tr + i*16)*IM + (w0 + tc + j*16)] = make_float2(ax, ay);
        }
}

// ---------------------------------------------------------------------------
// Kernel C: deterministic partial reduction + ortho scale + (re,im) interleave.
// ---------------------------------------------------------------------------
__global__ void __launch_bounds__(256) reduce_kernel(float* __restrict__ out)
{
    const int idx = blockIdx.x * 256 + threadIdx.x;  // 0 .. 65535 (u*256+w)
    float2 sum = make_float2(0.0f, 0.0f);
    #pragma unroll
    for (int c = 0; c < NCHUNK; ++c) {
        const float2 v = g_part[(size_t)c*(IM*IM) + idx];
        sum.x += v.x; sum.y += v.y;
    }
    out[2*idx]   = sum.x * ORTHO_F;
    out[2*idx+1] = sum.y * ORTHO_F;
}

extern "C" void kernel_launch(void* const* d_in, const int* in_sizes, int n_in,
                              void* d_out, int out_size)
{
    const float2* img  = (const float2*)d_in[0];  // x: (1,1,256,256,2)
    const float2* yrad = (const float2*)d_in[1];  // y_radial: (640,288,2)
    const float*  lam  = (const float*)d_in[2];   // lambda_param: (1,)
    const float*  ktr  = (const float*)d_in[3];   // ktraj: (1,2,M)
    const float*  kx = ktr;
    const float*  ky = ktr + MTOT;

    fwd_kernel<<<MTOT/256, 256>>>(img, yrad, lam, kx, ky);
    adj_kernel<<<dim3(8, NCHUNK), 256>>>(kx, ky);
    reduce_kernel<<<(IM*IM)/256, 256>>>((float*)d_out);
}